// round 8
// baseline (speedup 1.0000x reference)
#include <cuda_runtime.h>
#include <math.h>

#define ALPHA 10.0f
#define NPTS  4096
#define NB    4
#define NG    (2 * NB)            // dir * batch groups = 8

#define BLOCK 128                 // threads per block
#define RPT   8                   // rows per thread
#define JC    32                  // candidate chunks
#define CHUNK (NPTS / JC)         // 128 candidates per chunk
#define ROWTILES (NPTS / (BLOCK * RPT))  // 4
#define BLOCKS_PER_G (ROWTILES * JC)     // 128

#define VPT (NPTS / BLOCK)        // 32 key values per thread in the lse phase

// Row keys of t = 2*(a.b - w) - ||a||^2  (min dist = -t), monotone
// int-encoded, folded across chunk blocks with atomicMax. 128 KB.
__device__ int   g_rowmax[NG * NPTS];
__device__ float g_lse[NG];
__device__ unsigned int g_done[NG];   // per-group completion counters
__device__ unsigned int g_fin;        // final-stage counter

// Monotone float<->int order keys: key = (i>=0) ? i : i^0x7FFFFFFF.
// memset 0x80 => key 0x80808080 => ~-3.39e38 (below any real t here).
__device__ __forceinline__ int order_key(float f)
{
    int i = __float_as_int(f);
    return (i >= 0) ? i : (i ^ 0x7FFFFFFF);
}
__device__ __forceinline__ float order_unkey(int k)
{
    return __int_as_float((k >= 0) ? k : (k ^ 0x7FFFFFFF));
}

// ---------------------------------------------------------------------------
// Packed fp32x2 helpers (sm_100a native)
// ---------------------------------------------------------------------------
__device__ __forceinline__ unsigned long long ffma2(unsigned long long a,
                                                    unsigned long long b,
                                                    unsigned long long c)
{
    unsigned long long d;
    asm("fma.rn.f32x2 %0, %1, %2, %3;" : "=l"(d) : "l"(a), "l"(b), "l"(c));
    return d;
}

__device__ __forceinline__ unsigned long long pack2(float lo, float hi)
{
    unsigned long long r;
    asm("mov.b64 %0, {%1, %2};" : "=l"(r) : "f"(lo), "f"(hi));
    return r;
}

__device__ __forceinline__ void unpack2(unsigned long long v, float& lo, float& hi)
{
    asm("mov.b64 {%0, %1}, %2;" : "=f"(lo), "=f"(hi) : "l"(v));
}

// ---------------------------------------------------------------------------
// Fused kernel: chunk partial maxima -> atomicMax fold -> last block per
// group computes that group's logsumexp inline -> last group writes scalar.
// Hot loop per candidate: 2 LDS.128 + 12 FFMA2 + 8 FMNMX => 8 pairs/22 instr.
// ---------------------------------------------------------------------------
__global__ void __launch_bounds__(BLOCK)
hausdorff_fused_kernel(const float* __restrict__ p1,
                       const float* __restrict__ p2,
                       float* __restrict__ out)
{
    // Each candidate: {bx,bx} {by,by} {bz,bz} {-w,-w}  (w = 0.5*||b||^2)
    __shared__ ulonglong2 sB[CHUNK * 2];   // 4 KB
    __shared__ float red[BLOCK];
    __shared__ bool s_lastg, s_fin;

    const int g   = blockIdx.z;            // 0..7
    const int dir = g >> 2;
    const int b   = g & 3;
    const int jc  = blockIdx.y;
    const int tid = threadIdx.x;

    const float* __restrict__ A  = dir ? p2 : p1;
    const float* __restrict__ Bv = dir ? p1 : p2;
    const float* __restrict__ Bb = Bv + ((size_t)b * NPTS + jc * CHUNK) * 3;

    // Fill smem: exactly 1 candidate per thread (CHUNK == BLOCK).
    {
        const int j = tid;
        float x = Bb[3 * j + 0];
        float y = Bb[3 * j + 1];
        float z = Bb[3 * j + 2];
        float w = -0.5f * (x * x + y * y + z * z);
        sB[2 * j + 0] = make_ulonglong2(pack2(x, x), pack2(y, y));
        sB[2 * j + 1] = make_ulonglong2(pack2(z, z), pack2(w, w));
    }
    __syncthreads();

    // Load 8 rows (strided by BLOCK for coalescing) and pack pairs.
    const int rowbase = blockIdx.x * (BLOCK * RPT);
    float ax[RPT], ay[RPT], az[RPT];
#pragma unroll
    for (int k = 0; k < RPT; ++k) {
        const int i = rowbase + tid + k * BLOCK;
        const float* __restrict__ Ai = A + ((size_t)b * NPTS + i) * 3;
        ax[k] = Ai[0];
        ay[k] = Ai[1];
        az[k] = Ai[2];
    }
    unsigned long long pax[RPT / 2], pay[RPT / 2], paz[RPT / 2];
#pragma unroll
    for (int p = 0; p < RPT / 2; ++p) {
        pax[p] = pack2(ax[2 * p], ax[2 * p + 1]);
        pay[p] = pack2(ay[2 * p], ay[2 * p + 1]);
        paz[p] = pack2(az[2 * p], az[2 * p + 1]);
    }

    float m[RPT];
#pragma unroll
    for (int k = 0; k < RPT; ++k) m[k] = -3.402823466e38f;

#pragma unroll 4
    for (int j = 0; j < CHUNK; ++j) {
        const ulonglong2 q0 = sB[2 * j + 0];   // {bx,bx} {by,by}
        const ulonglong2 q1 = sB[2 * j + 1];   // {bz,bz} {-w,-w}
#pragma unroll
        for (int p = 0; p < RPT / 2; ++p) {
            unsigned long long s = ffma2(pax[p], q0.x, q1.y);
            s = ffma2(pay[p], q0.y, s);
            s = ffma2(paz[p], q1.x, s);
            float s0, s1;
            unpack2(s, s0, s1);
            m[2 * p + 0] = fmaxf(m[2 * p + 0], s0);
            m[2 * p + 1] = fmaxf(m[2 * p + 1], s1);
        }
    }

    // Fold t = 2*m - sq into the per-row key (max: order-independent).
#pragma unroll
    for (int k = 0; k < RPT; ++k) {
        const int row = rowbase + tid + k * BLOCK;
        const float sq = fmaf(ax[k], ax[k], fmaf(ay[k], ay[k], az[k] * az[k]));
        const float t  = fmaf(2.0f, m[k], -sq);
        atomicMax(&g_rowmax[g * NPTS + row], order_key(t));
    }

    // Elect the last-finishing block of this group.
    if (tid == 0) {
        __threadfence();
        unsigned int prev = atomicAdd(&g_done[g], 1u);
        s_lastg = (prev == BLOCKS_PER_G - 1);
    }
    __syncthreads();
    if (!s_lastg) return;

    // ---- Inline logsumexp for group g (keys complete; read via L2). ----
    const int4* __restrict__ keys = (const int4*)(g_rowmax + g * NPTS);
    float v[VPT];
#pragma unroll
    for (int q = 0; q < VPT / 4; ++q) {            // 8 x LDG.128 (.cg)
        int4 kk = __ldcg(&keys[tid + q * BLOCK]);
        v[4 * q + 0] = -ALPHA * order_unkey(kk.x);
        v[4 * q + 1] = -ALPHA * order_unkey(kk.y);
        v[4 * q + 2] = -ALPHA * order_unkey(kk.z);
        v[4 * q + 3] = -ALPHA * order_unkey(kk.w);
    }

    float M = v[0];
#pragma unroll
    for (int r = 1; r < VPT; ++r) M = fmaxf(M, v[r]);
    red[tid] = M;
    __syncthreads();
    for (int s = BLOCK / 2; s > 0; s >>= 1) {
        if (tid < s) red[tid] = fmaxf(red[tid], red[tid + s]);
        __syncthreads();
    }
    M = red[0];
    __syncthreads();

    float acc = 0.0f;
#pragma unroll
    for (int r = 0; r < VPT; ++r) acc += expf(v[r] - M);
    red[tid] = acc;
    __syncthreads();
    for (int s = BLOCK / 2; s > 0; s >>= 1) {
        if (tid < s) red[tid] += red[tid + s];
        __syncthreads();
    }

    if (tid == 0) {
        g_lse[g] = (M + logf(red[0])) / ALPHA;
        __threadfence();
        unsigned int prev = atomicAdd(&g_fin, 1u);
        s_fin = (prev == NG - 1);
    }
    __syncthreads();

    // Last group's elected block writes the scalar (fixed order: determinist).
    if (s_fin && tid == 0) {
        float a = 0.0f, c = 0.0f;
        for (int i = 0; i < NB; ++i) {
            a += __ldcg(&g_lse[i]);
            c += __ldcg(&g_lse[NB + i]);
        }
        out[0] = 0.5f * (a / NB + c / NB);
    }
}

// ---------------------------------------------------------------------------
extern "C" void kernel_launch(void* const* d_in, const int* in_sizes, int n_in,
                              void* d_out, int out_size)
{
    const float* p1 = (const float*)d_in[0];
    const float* p2 = (const float*)d_in[1];
    float* out = (float*)d_out;

    // Reset keys to ~-3.39e38 (order-key 0x80808080) and counters to 0.
    // Async memsets are graph-capturable; no allocation.
    void* rm = nullptr;
    cudaGetSymbolAddress(&rm, g_rowmax);
    cudaMemsetAsync(rm, 0x80, NG * NPTS * sizeof(int));
    void* dn = nullptr;
    cudaGetSymbolAddress(&dn, g_done);
    cudaMemsetAsync(dn, 0, NG * sizeof(unsigned int));
    void* fn = nullptr;
    cudaGetSymbolAddress(&fn, g_fin);
    cudaMemsetAsync(fn, 0, sizeof(unsigned int));

    dim3 grid(ROWTILES, JC, NG);   // 4 x 32 x 8 = 1024 blocks
    hausdorff_fused_kernel<<<grid, BLOCK>>>(p1, p2, out);
}

// round 10
// speedup vs baseline: 1.1929x; 1.1929x over previous
#include <cuda_runtime.h>
#include <math.h>

#define ALPHA 10.0f
#define NPTS  4096
#define NB    4
#define NG    (2 * NB)            // dir * batch groups = 8

#define BLOCK 128                 // threads per block (kernel 1)
#define RPT   8                   // rows per thread
#define JC    64                  // candidate chunks
#define CHUNK (NPTS / JC)         // 64 candidates per chunk
#define ROWTILES (NPTS / (BLOCK * RPT))  // 4

#define LSE_BLOCK 256
#define LSE_RPT   (NPTS / LSE_BLOCK)     // 16

// Row keys of t = 2*(a.b - w) - ||a||^2  (so min dist = -t), as monotone
// int-encoded floats folded across chunk blocks with atomicMax. 128 KB.
__device__ int   g_rowmax[NG * NPTS];
__device__ float g_lse[NG];
__device__ unsigned int g_ctr;

// Monotone float<->int order keys: key = (i>=0) ? i : i^0x7FFFFFFF.
// memset 0x80 => key 0x80808080 => ~-3.39e38 (below any real t here).
__device__ __forceinline__ int order_key(float f)
{
    int i = __float_as_int(f);
    return (i >= 0) ? i : (i ^ 0x7FFFFFFF);
}
__device__ __forceinline__ float order_unkey(int k)
{
    return __int_as_float((k >= 0) ? k : (k ^ 0x7FFFFFFF));
}

// ---------------------------------------------------------------------------
// Packed fp32x2 helpers (sm_100a native)
// ---------------------------------------------------------------------------
__device__ __forceinline__ unsigned long long ffma2(unsigned long long a,
                                                    unsigned long long b,
                                                    unsigned long long c)
{
    unsigned long long d;
    asm("fma.rn.f32x2 %0, %1, %2, %3;" : "=l"(d) : "l"(a), "l"(b), "l"(c));
    return d;
}

__device__ __forceinline__ unsigned long long pack2(float lo, float hi)
{
    unsigned long long r;
    asm("mov.b64 %0, {%1, %2};" : "=l"(r) : "f"(lo), "f"(hi));
    return r;
}

__device__ __forceinline__ void unpack2(unsigned long long v, float& lo, float& hi)
{
    asm("mov.b64 {%0, %1}, %2;" : "=f"(lo), "=f"(hi) : "l"(v));
}

// ---------------------------------------------------------------------------
// Kernel 1: per (group, row) fold max_j of t = 2*(a.b - w) - ||a||^2 across
// candidate chunks with atomicMax on order-keys. Hot loop per candidate:
// 2 LDS.128 + 12 FFMA2 + 8 FMNMX => 8 pairs / 22 instrs.
// ---------------------------------------------------------------------------
__global__ void __launch_bounds__(BLOCK)
hausdorff_part_kernel(const float* __restrict__ p1,
                      const float* __restrict__ p2)
{
    // Each candidate: {bx,bx} {by,by} {bz,bz} {-w,-w}  (w = 0.5*||b||^2)
    __shared__ ulonglong2 sB[CHUNK * 2];   // 2 KB

    const int g   = blockIdx.z;            // 0..7
    const int dir = g >> 2;
    const int b   = g & 3;
    const int jc  = blockIdx.y;
    const int tid = threadIdx.x;

    if (blockIdx.x == 0 && blockIdx.y == 0 && blockIdx.z == 0 && tid == 0)
        g_ctr = 0;

    const float* __restrict__ A  = dir ? p2 : p1;
    const float* __restrict__ Bv = dir ? p1 : p2;
    const float* __restrict__ Bb = Bv + ((size_t)b * NPTS + jc * CHUNK) * 3;

    // Fill smem: CHUNK(=64) candidates, threads 0..63.
    if (tid < CHUNK) {
        const int j = tid;
        float x = Bb[3 * j + 0];
        float y = Bb[3 * j + 1];
        float z = Bb[3 * j + 2];
        float w = -0.5f * (x * x + y * y + z * z);
        sB[2 * j + 0] = make_ulonglong2(pack2(x, x), pack2(y, y));
        sB[2 * j + 1] = make_ulonglong2(pack2(z, z), pack2(w, w));
    }
    __syncthreads();

    // Load 8 rows (strided by BLOCK for coalescing) and pack pairs.
    const int rowbase = blockIdx.x * (BLOCK * RPT);
    float ax[RPT], ay[RPT], az[RPT];
#pragma unroll
    for (int k = 0; k < RPT; ++k) {
        const int i = rowbase + tid + k * BLOCK;
        const float* __restrict__ Ai = A + ((size_t)b * NPTS + i) * 3;
        ax[k] = Ai[0];
        ay[k] = Ai[1];
        az[k] = Ai[2];
    }
    unsigned long long pax[RPT / 2], pay[RPT / 2], paz[RPT / 2];
#pragma unroll
    for (int p = 0; p < RPT / 2; ++p) {
        pax[p] = pack2(ax[2 * p], ax[2 * p + 1]);
        pay[p] = pack2(ay[2 * p], ay[2 * p + 1]);
        paz[p] = pack2(az[2 * p], az[2 * p + 1]);
    }

    float m[RPT];
#pragma unroll
    for (int k = 0; k < RPT; ++k) m[k] = -3.402823466e38f;

#pragma unroll 4
    for (int j = 0; j < CHUNK; ++j) {
        const ulonglong2 q0 = sB[2 * j + 0];   // {bx,bx} {by,by}
        const ulonglong2 q1 = sB[2 * j + 1];   // {bz,bz} {-w,-w}
#pragma unroll
        for (int p = 0; p < RPT / 2; ++p) {
            unsigned long long s = ffma2(pax[p], q0.x, q1.y);
            s = ffma2(pay[p], q0.y, s);
            s = ffma2(paz[p], q1.x, s);
            float s0, s1;
            unpack2(s, s0, s1);
            m[2 * p + 0] = fmaxf(m[2 * p + 0], s0);
            m[2 * p + 1] = fmaxf(m[2 * p + 1], s1);
        }
    }

    // Fold sq into the key so the lse kernel never touches the points:
    // t = 2*m - sq;  min dist = -t.  Max is order-independent => determinist.
#pragma unroll
    for (int k = 0; k < RPT; ++k) {
        const int row = rowbase + tid + k * BLOCK;
        const float sq = fmaf(ax[k], ax[k], fmaf(ay[k], ay[k], az[k] * az[k]));
        const float t  = fmaf(2.0f, m[k], -sq);
        atomicMax(&g_rowmax[g * NPTS + row], order_key(t));
    }
}

// ---------------------------------------------------------------------------
// Kernel 2 (fused lse + final): reads ONLY the 16KB/group key array (int4,
// coalesced, L2-hot). v = -ALPHA * t. Last block writes the scalar.
// ---------------------------------------------------------------------------
__global__ void __launch_bounds__(LSE_BLOCK)
hausdorff_lse_kernel(float* __restrict__ out)
{
    __shared__ float red[LSE_BLOCK];
    __shared__ bool s_last;

    const int g   = blockIdx.x;
    const int tid = threadIdx.x;

    const int4* __restrict__ keys = (const int4*)(g_rowmax + g * NPTS);

    float v[LSE_RPT];
#pragma unroll
    for (int q = 0; q < LSE_RPT / 4; ++q) {          // 4 x LDG.128, coalesced
        int4 kk = keys[tid + q * LSE_BLOCK];
        v[4 * q + 0] = -ALPHA * order_unkey(kk.x);
        v[4 * q + 1] = -ALPHA * order_unkey(kk.y);
        v[4 * q + 2] = -ALPHA * order_unkey(kk.z);
        v[4 * q + 3] = -ALPHA * order_unkey(kk.w);
    }

    // group max
    float M = v[0];
#pragma unroll
    for (int r = 1; r < LSE_RPT; ++r) M = fmaxf(M, v[r]);
    red[tid] = M;
    __syncthreads();
    for (int s = LSE_BLOCK / 2; s > 0; s >>= 1) {
        if (tid < s) red[tid] = fmaxf(red[tid], red[tid + s]);
        __syncthreads();
    }
    M = red[0];
    __syncthreads();

    // sum exp
    float acc = 0.0f;
#pragma unroll
    for (int r = 0; r < LSE_RPT; ++r) acc += expf(v[r] - M);
    red[tid] = acc;
    __syncthreads();
    for (int s = LSE_BLOCK / 2; s > 0; s >>= 1) {
        if (tid < s) red[tid] += red[tid + s];
        __syncthreads();
    }

    if (tid == 0) {
        g_lse[g] = (M + logf(red[0])) / ALPHA;
        __threadfence();
        unsigned int prev = atomicAdd(&g_ctr, 1u);
        s_last = (prev == NG - 1);
    }
    __syncthreads();

    if (s_last && tid == 0) {
        float a = 0.0f, c = 0.0f;
        for (int i = 0; i < NB; ++i) {
            a += g_lse[i];
            c += g_lse[NB + i];
        }
        out[0] = 0.5f * (a / NB + c / NB);
    }
}

// ---------------------------------------------------------------------------
extern "C" void kernel_launch(void* const* d_in, const int* in_sizes, int n_in,
                              void* d_out, int out_size)
{
    const float* p1 = (const float*)d_in[0];
    const float* p2 = (const float*)d_in[1];
    float* out = (float*)d_out;

    // Reset row keys to ~-3.39e38 (order-key 0x80808080). Capturable async
    // memset, no allocation.
    void* rm = nullptr;
    cudaGetSymbolAddress(&rm, g_rowmax);
    cudaMemsetAsync(rm, 0x80, NG * NPTS * sizeof(int));

    dim3 grid(ROWTILES, JC, NG);   // 4 x 64 x 8 = 2048 blocks
    hausdorff_part_kernel<<<grid, BLOCK>>>(p1, p2);
    hausdorff_lse_kernel<<<NG, LSE_BLOCK>>>(out);
}